// round 8
// baseline (speedup 1.0000x reference)
#include <cuda_runtime.h>
#include <stdint.h>
#include <math.h>

// q,k,v: (B=2, S=2048, H=16, C=64) f32 ; bias: (B,H,S,S) f32 ; m: (B,S) i32 sorted
// out: (B,S,H,C) f32
namespace {

constexpr int SEQ = 2048;
constexpr int H_  = 16;
constexpr int C_  = 64;
constexpr int BQ  = 64;
constexpr int BK  = 64;
constexpr int ST  = 68;            // smem row stride in 32-bit words (272B, 16B-aligned)
constexpr float SM_SCALE = 0.125f; // 1/sqrt(64)

__device__ __forceinline__ uint32_t f2tf(float x) {
    uint32_t y;
    asm("cvt.rna.tf32.f32 %0, %1;" : "=r"(y) : "f"(x));
    return y;
}

__device__ __forceinline__ uint32_t s2u(const void* p) {
    uint32_t a;
    asm("{ .reg .u64 t; cvta.to.shared.u64 t, %1; cvt.u32.u64 %0, t; }" : "=r"(a) : "l"(p));
    return a;
}

// ldmatrix x4 on b16: for tf32 data this yields, per 8x8(k=8) f32 quadrant,
// thread t <- element (row t/4, col t%4) -- exactly the tf32 mma fragment layout.
__device__ __forceinline__ void ldmx4(uint32_t* r, uint32_t addr) {
    asm volatile("ldmatrix.sync.aligned.m8n8.x4.shared.b16 {%0,%1,%2,%3}, [%4];"
        : "=r"(r[0]), "=r"(r[1]), "=r"(r[2]), "=r"(r[3]) : "r"(addr));
}

__device__ __forceinline__ void mma8(float* d, const uint32_t* a, const uint32_t* b) {
    asm volatile(
        "mma.sync.aligned.m16n8k8.row.col.f32.tf32.tf32.f32 "
        "{%0,%1,%2,%3}, {%4,%5,%6,%7}, {%8,%9}, {%0,%1,%2,%3};"
        : "+f"(d[0]), "+f"(d[1]), "+f"(d[2]), "+f"(d[3])
        : "r"(a[0]), "r"(a[1]), "r"(a[2]), "r"(a[3]), "r"(b[0]), "r"(b[1]));
}

__global__ void __launch_bounds__(128)
attn_mma(const float* __restrict__ q, const float* __restrict__ k,
         const float* __restrict__ v, const float* __restrict__ bias,
         const int* __restrict__ m, float* __restrict__ out)
{
    extern __shared__ float smem[];
    float* Qs = smem;                 // BQ x ST (tf32 bits)
    float* Ks = Qs + BQ * ST;         // BK x ST (tf32 bits)
    float* Vs = Ks + BK * ST;         // BK x ST (tf32 bits)
    float* Ps = Vs + BK * ST;         // BQ x ST (tf32 bits), per-warp private rows

    const uint32_t sbQ = s2u(Qs);
    const uint32_t sbK = s2u(Ks);
    const uint32_t sbP = s2u(Ps);

    // heavy q-tiles first for tail balance
    const int qt = (int)gridDim.x - 1 - (int)blockIdx.x;
    const int h  = blockIdx.y;
    const int b  = blockIdx.z;
    const int q0 = qt * BQ;

    const int tid  = threadIdx.x;
    const int w    = tid >> 5;
    const int lane = tid & 31;
    const int g    = lane >> 2;   // group id 0..7
    const int tig  = lane & 3;    // thread in group 0..3
    const int r0   = 16 * w + g;  // my rows within the q-tile
    const int r1   = r0 + 8;
    const int qrow0 = q0 + r0;
    const int qrow1 = q0 + r1;

    // ldmatrix per-lane address components
    const int lane7 = lane & 7;
    const int lhr   = (lane >> 3) & 1;   // matrix-pair selector (row+8 for A, col+4 for B)
    const int lq    = lane >> 4;         // (col+4 for A, row-group for B)
    // A-operand (Q or P tile): m0: rows 16w+0..7 cols s..s+3 ; m1: rows+8 ; m2: cols+4 ; m3: both
    const uint32_t aoff = (uint32_t)(((16 * w + lane7 + 8 * lhr) * ST + 4 * lq) * 4);
    // B-operand (K tile): m0: rows 16ntp+0..7 colchunk lo ; m1: col hi ; m2: rows+8 (nt odd) ; m3: both
    const uint32_t boff = (uint32_t)(((8 * lq + lane7) * ST + 4 * lhr) * 4);

    const size_t qkv_base = ((size_t)(b * SEQ) * H_ + h) * C_;
    const float* qp = q + qkv_base + (size_t)q0 * H_ * C_;
    const float* kp = k + qkv_base;
    const float* vp = v + qkv_base;
    const float* bp = bias + ((size_t)(b * H_ + h)) * SEQ * SEQ;
    const int*   mb = m + b * SEQ;

    // ---- load Q tile, convert to tf32 once ----
    #pragma unroll
    for (int i = 0; i < 8; i++) {
        int idx = tid + i * 128;
        int r = idx >> 4, c4 = idx & 15;
        float4 t = *(const float4*)(qp + (size_t)r * H_ * C_ + c4 * 4);
        uint4 u = { f2tf(t.x), f2tf(t.y), f2tf(t.z), f2tf(t.w) };
        *(uint4*)(Qs + r * ST + c4 * 4) = u;
    }

    // ---- segment bounds: m sorted => mask(q,k) = (k >= lower_bound(m[q])) && (k <= q)
    const int seg0 = mb[qrow0];
    const int seg1 = mb[qrow1];
    const int segt = mb[q0];
    auto lbound = [&](int key) {
        int lo = 0, hi = q0 + BQ;
        while (lo < hi) { int mid = (lo + hi) >> 1; if (mb[mid] < key) lo = mid + 1; else hi = mid; }
        return lo;
    };
    const int lo0 = lbound(seg0);
    const int lo1 = lbound(seg1);
    const int kt_start = lbound(segt) >> 6;   // uniform across CTA

    float oa[8][4];
    #pragma unroll
    for (int nt = 0; nt < 8; nt++) {
        #pragma unroll
        for (int i = 0; i < 4; i++) oa[nt][i] = 0.f;
    }
    float mi0 = -1e30f, mi1 = -1e30f, li0 = 0.f, li1 = 0.f;

    const uint32_t* Vu = (const uint32_t*)Vs;
    uint32_t*       Pu = (uint32_t*)Ps;

    for (int kt = kt_start; kt <= qt; kt++) {
        const int k0 = kt * BK;
        __syncthreads();  // protect Ks/Vs/Ps against previous iteration readers

        // ---- load K,V tiles, convert to tf32 ----
        #pragma unroll
        for (int i = 0; i < 8; i++) {
            int idx = tid + i * 128;
            int r = idx >> 4, c4 = idx & 15;
            float4 tk = *(const float4*)(kp + (size_t)(k0 + r) * H_ * C_ + c4 * 4);
            float4 tv = *(const float4*)(vp + (size_t)(k0 + r) * H_ * C_ + c4 * 4);
            uint4 uk = { f2tf(tk.x), f2tf(tk.y), f2tf(tk.z), f2tf(tk.w) };
            uint4 uv = { f2tf(tv.x), f2tf(tv.y), f2tf(tv.z), f2tf(tv.w) };
            *(uint4*)(Ks + r * ST + c4 * 4) = uk;
            *(uint4*)(Vs + r * ST + c4 * 4) = uv;
        }
        __syncthreads();

        // ---- bias prefetch (predicated float2, 32B sector aligned) — overlaps QK MMA ----
        float2 bf0[8], bf1[8];
        #pragma unroll
        for (int nt = 0; nt < 8; nt++) {
            const int kc = k0 + 8 * nt + 2 * tig;
            const bool a0 = (kc >= lo0) & (kc <= qrow0);
            const bool a1 = (kc + 1 >= lo0) & (kc + 1 <= qrow0);
            const bool c0 = (kc >= lo1) & (kc <= qrow1);
            const bool c1 = (kc + 1 >= lo1) & (kc + 1 <= qrow1);
            bf0[nt] = (a0 | a1) ? *(const float2*)(bp + (size_t)qrow0 * SEQ + kc)
                                : make_float2(0.f, 0.f);
            bf1[nt] = (c0 | c1) ? *(const float2*)(bp + (size_t)qrow1 * SEQ + kc)
                                : make_float2(0.f, 0.f);
        }

        // ---- S = Q K^T via tf32 MMA, fragments via ldmatrix ----
        float sa[8][4];
        #pragma unroll
        for (int nt = 0; nt < 8; nt++) {
            #pragma unroll
            for (int i = 0; i < 4; i++) sa[nt][i] = 0.f;
        }
        #pragma unroll
        for (int s = 0; s < 8; s++) {
            uint32_t aq[4];
            ldmx4(aq, sbQ + aoff + s * 32);
            #pragma unroll
            for (int ntp = 0; ntp < 4; ntp++) {
                uint32_t bb[4];   // {b0,b1} for nt=2ntp ; {b2,b3} for nt=2ntp+1
                ldmx4(bb, sbK + boff + (uint32_t)(ntp * (16 * ST * 4)) + s * 32);
                mma8(sa[2 * ntp],     aq, bb);
                mma8(sa[2 * ntp + 1], aq, bb + 2);
            }
        }

        // ---- mask + bias, row max ----
        float rm0 = -1e30f, rm1 = -1e30f;
        #pragma unroll
        for (int nt = 0; nt < 8; nt++) {
            const int kc = k0 + 8 * nt + 2 * tig;
            const bool o00 = (kc >= lo0) & (kc <= qrow0);
            const bool o01 = (kc + 1 >= lo0) & (kc + 1 <= qrow0);
            const bool o10 = (kc >= lo1) & (kc <= qrow1);
            const bool o11 = (kc + 1 >= lo1) & (kc + 1 <= qrow1);
            sa[nt][0] = o00 ? fmaf(sa[nt][0], SM_SCALE, bf0[nt].x) : -1e30f;
            sa[nt][1] = o01 ? fmaf(sa[nt][1], SM_SCALE, bf0[nt].y) : -1e30f;
            sa[nt][2] = o10 ? fmaf(sa[nt][2], SM_SCALE, bf1[nt].x) : -1e30f;
            sa[nt][3] = o11 ? fmaf(sa[nt][3], SM_SCALE, bf1[nt].y) : -1e30f;
            rm0 = fmaxf(rm0, fmaxf(sa[nt][0], sa[nt][1]));
            rm1 = fmaxf(rm1, fmaxf(sa[nt][2], sa[nt][3]));
        }
        rm0 = fmaxf(rm0, __shfl_xor_sync(0xffffffffu, rm0, 1));
        rm0 = fmaxf(rm0, __shfl_xor_sync(0xffffffffu, rm0, 2));
        rm1 = fmaxf(rm1, __shfl_xor_sync(0xffffffffu, rm1, 1));
        rm1 = fmaxf(rm1, __shfl_xor_sync(0xffffffffu, rm1, 2));

        const float mn0 = fmaxf(mi0, rm0);
        const float mn1 = fmaxf(mi1, rm1);
        const float al0 = __expf(mi0 - mn0);
        const float al1 = __expf(mi1 - mn1);
        mi0 = mn0; mi1 = mn1;

        // ---- exp + P store (tf32, vectorized STS.64). Masked entries give
        // exp(-1e30 - mn) == 0 for finite mn; all-dead-tile junk is killed by
        // alpha==0 at the first live tile.
        float rs0 = 0.f, rs1 = 0.f;
        #pragma unroll
        for (int nt = 0; nt < 8; nt++) {
            float p00 = __expf(sa[nt][0] - mn0);
            float p01 = __expf(sa[nt][1] - mn0);
            float p10 = __expf(sa[nt][2] - mn1);
            float p11 = __expf(sa[nt][3] - mn1);
            rs0 += p00 + p01;
            rs1 += p10 + p11;
            const int cc = 8 * nt + 2 * tig;
            *(uint2*)(Pu + r0 * ST + cc) = make_uint2(f2tf(p00), f2tf(p01));
            *(uint2*)(Pu + r1 * ST + cc) = make_uint2(f2tf(p10), f2tf(p11));
        }
        rs0 += __shfl_xor_sync(0xffffffffu, rs0, 1);
        rs0 += __shfl_xor_sync(0xffffffffu, rs0, 2);
        rs1 += __shfl_xor_sync(0xffffffffu, rs1, 1);
        rs1 += __shfl_xor_sync(0xffffffffu, rs1, 2);
        li0 = li0 * al0 + rs0;
        li1 = li1 * al1 + rs1;

        #pragma unroll
        for (int nt = 0; nt < 8; nt++) {
            oa[nt][0] *= al0; oa[nt][1] *= al0;
            oa[nt][2] *= al1; oa[nt][3] *= al1;
        }

        __syncwarp();  // P rows 16w..16w+15 written & read only by warp w

        // ---- O += P V : A via ldmatrix, B via scalar LDS (V row-major, col-major frag) ----
        #pragma unroll
        for (int s = 0; s < 8; s++) {
            uint32_t ap[4];
            ldmx4(ap, sbP + aoff + s * 32);
            #pragma unroll
            for (int nt = 0; nt < 8; nt++) {
                uint32_t bb[2];
                bb[0] = Vu[(8 * s + tig) * ST + 8 * nt + g];
                bb[1] = Vu[(8 * s + tig + 4) * ST + 8 * nt + g];
                mma8(oa[nt], ap, bb);
            }
        }
    }

    // ---- normalize + store ----
    const float inv0 = 1.f / li0;
    const float inv1 = 1.f / li1;
    float* op0 = out + ((size_t)(b * SEQ + qrow0) * H_ + h) * C_;
    float* op1 = out + ((size_t)(b * SEQ + qrow1) * H_ + h) * C_;
    #pragma unroll
    for (int nt = 0; nt < 8; nt++) {
        const int cc = 8 * nt + 2 * tig;
        *(float2*)(op0 + cc) = make_float2(oa[nt][0] * inv0, oa[nt][1] * inv0);
        *(float2*)(op1 + cc) = make_float2(oa[nt][2] * inv1, oa[nt][3] * inv1);
    }
}

constexpr int SMEM_BYTES = 4 * BQ * ST * (int)sizeof(float);  // 69,632 B

} // namespace

extern "C" void kernel_launch(void* const* d_in, const int* in_sizes, int n_in,
                              void* d_out, int out_size)
{
    (void)in_sizes; (void)n_in; (void)out_size;
    const float* q    = (const float*)d_in[0];
    const float* k    = (const float*)d_in[1];
    const float* v    = (const float*)d_in[2];
    const float* bias = (const float*)d_in[3];
    const int*   m    = (const int*)d_in[4];
    float* out = (float*)d_out;

    cudaFuncSetAttribute(attn_mma,
                         cudaFuncAttributeMaxDynamicSharedMemorySize, SMEM_BYTES);

    dim3 grid(SEQ / BQ, H_, 2);  // (32, 16, 2)
    attn_mma<<<grid, 128, SMEM_BYTES>>>(q, k, v, bias, m, out);
}